// round 15
// baseline (speedup 1.0000x reference)
#include <cuda_runtime.h>

#define BB 256
#define TT 256
#define DD 128
#define HHH 256

typedef unsigned long long u64t;
typedef unsigned int u32t;

// Blackwell packed fp32 ops (PTX-only)
#define FMA2(d,a,b,c) asm("fma.rn.f32x2 %0, %1, %2, %3;" : "=l"(d) : "l"(a), "l"(b), "l"(c))
#define PACK1(d,x)    asm("mov.b64 %0, {%1, %1};" : "=l"(d) : "r"(x))
#define UNPK(lo,hi,v) asm("mov.b64 {%0, %1}, %2;" : "=r"(lo), "=r"(hi) : "l"(v))

#define CLUSTER_ARRIVE() asm volatile("barrier.cluster.arrive.aligned;" ::: "memory")
#define CLUSTER_WAIT()   asm volatile("barrier.cluster.wait.aligned;" ::: "memory")

__device__ __forceinline__ void dsmem_st64(u32t laddr, int rank, u64t v) {
    u32t ra;
    asm volatile("mapa.shared::cluster.u32 %0, %1, %2;" : "=r"(ra) : "r"(laddr), "r"(rank));
    asm volatile("st.shared::cluster.b64 [%0], %1;" :: "r"(ra), "l"(v) : "memory");
}
__device__ __forceinline__ void dsmem_st32(u32t laddr, int rank, float v) {
    u32t ra;
    asm volatile("mapa.shared::cluster.u32 %0, %1, %2;" : "=r"(ra) : "r"(laddr), "r"(rank));
    asm volatile("st.shared::cluster.f32 [%0], %1;" :: "r"(ra), "f"(v) : "memory");
}

// ---------------- scratch (device globals; no allocations) ----------------
__device__ float g_xproj_enc[(size_t)BB * TT * 4 * HHH];  // 256 MB
__device__ float g_xproj_dec[(size_t)BB * TT * 4 * DD];   // 128 MB
__device__ float g_enc_out[(size_t)BB * TT * HHH];        // 64 MB

__global__ void dummy_kernel() {}

// ---------------- input-projection GEMM: C[M,N] = A[M,K] @ W[N,K]^T + b1 + b2
// 128x128 tiles, BK=8, 256 threads, 8x8 micro-tile, packed f32x2 FMA.
template <int K>
__global__ __launch_bounds__(256) void proj_kernel(
    const float* __restrict__ Ain, const float* __restrict__ W,
    const float* __restrict__ b1, const float* __restrict__ b2,
    int src_sel, int dst_sel, int N)
{
    const float* A = src_sel ? (const float*)g_enc_out : Ain;
    float* C = dst_sel ? (float*)g_xproj_dec : (float*)g_xproj_enc;

    __shared__ float As[8][128];
    __shared__ float Bs[8][128];
    int tid = threadIdx.x;
    int bn = blockIdx.x, bm = blockIdx.y;
    int tr = tid >> 4, tc = tid & 15;
    int lr = tid >> 1;
    int lk = (tid & 1) << 2;

    const float* Ag = A + (size_t)(bm * 128 + lr) * K + lk;
    const float* Wg = W + (size_t)(bn * 128 + lr) * K + lk;

    u64t acc[8][4];
#pragma unroll
    for (int i = 0; i < 8; ++i)
#pragma unroll
        for (int j = 0; j < 4; ++j) acc[i][j] = 0ULL;

    for (int kb = 0; kb < K; kb += 8) {
        float4 av = *(const float4*)(Ag + kb);
        float4 wv = *(const float4*)(Wg + kb);
        __syncthreads();
        As[lk + 0][lr] = av.x; As[lk + 1][lr] = av.y;
        As[lk + 2][lr] = av.z; As[lk + 3][lr] = av.w;
        Bs[lk + 0][lr] = wv.x; Bs[lk + 1][lr] = wv.y;
        Bs[lk + 2][lr] = wv.z; Bs[lk + 3][lr] = wv.w;
        __syncthreads();
#pragma unroll
        for (int kk = 0; kk < 8; ++kk) {
            float4 alo = *(const float4*)&As[kk][tr * 4];
            float4 ahi = *(const float4*)&As[kk][64 + tr * 4];
            ulonglong2 wlo = *(const ulonglong2*)&Bs[kk][tc * 4];
            ulonglong2 whi = *(const ulonglong2*)&Bs[kk][64 + tc * 4];
            float ar[8] = {alo.x, alo.y, alo.z, alo.w, ahi.x, ahi.y, ahi.z, ahi.w};
#pragma unroll
            for (int i = 0; i < 8; ++i) {
                u64t a2; PACK1(a2, __float_as_uint(ar[i]));
                FMA2(acc[i][0], a2, wlo.x, acc[i][0]);
                FMA2(acc[i][1], a2, wlo.y, acc[i][1]);
                FMA2(acc[i][2], a2, whi.x, acc[i][2]);
                FMA2(acc[i][3], a2, whi.y, acc[i][3]);
            }
        }
    }
    int c_lo = bn * 128 + tc * 4;
    int c_hi = c_lo + 64;
    float4 v1 = *(const float4*)&b1[c_lo];
    float4 v2 = *(const float4*)&b2[c_lo];
    float4 blo = make_float4(v1.x + v2.x, v1.y + v2.y, v1.z + v2.z, v1.w + v2.w);
    float4 u1 = *(const float4*)&b1[c_hi];
    float4 u2 = *(const float4*)&b2[c_hi];
    float4 bhi = make_float4(u1.x + u2.x, u1.y + u2.y, u1.z + u2.z, u1.w + u2.w);
#pragma unroll
    for (int i = 0; i < 8; ++i) {
        int row = bm * 128 + (i < 4 ? tr * 4 + i : 64 + tr * 4 + (i - 4));
        u32t l0, h0, l1, h1;
        UNPK(l0, h0, acc[i][0]); UNPK(l1, h1, acc[i][1]);
        float4 o0 = make_float4(__uint_as_float(l0) + blo.x, __uint_as_float(h0) + blo.y,
                                __uint_as_float(l1) + blo.z, __uint_as_float(h1) + blo.w);
        *(float4*)&C[(size_t)row * N + c_lo] = o0;
        UNPK(l0, h0, acc[i][2]); UNPK(l1, h1, acc[i][3]);
        float4 o1 = make_float4(__uint_as_float(l0) + bhi.x, __uint_as_float(h0) + bhi.y,
                                __uint_as_float(l1) + bhi.z, __uint_as_float(h1) + bhi.w);
        *(float4*)&C[(size_t)row * N + c_hi] = o1;
    }
}

// ---------------- encoder recurrence: 16 clusters x 8 CTAs ----------------
// Cluster = 16 batch rows. CTA = rank, owns 32 neurons (128 gate cols).
// Ws[256][128] 128KB + Hs[2][16][256] 32KB + Gs[16][132] 8.25KB = 168.25KB
#define ENC_WS_F   (256 * 128)
#define ENC_HS_F   (2 * 16 * 256)
#define ENC_GS_F   (16 * 132)
#define ENC_SMEM_BYTES ((ENC_WS_F + ENC_HS_F + ENC_GS_F) * 4)

__global__ __launch_bounds__(256) __cluster_dims__(8, 1, 1)
void enc_rec_kernel(const float* __restrict__ Whh)
{
    extern __shared__ float sm[];
    float (*Ws)[128] = (float(*)[128])sm;                       // [k][c], c=gate*32+jj
    float (*Hs)[16][256] = (float(*)[16][256])(sm + ENC_WS_F);  // [buf][row][k]
    float (*Gs)[132] = (float(*)[132])(sm + ENC_WS_F + ENC_HS_F);

    int tid = threadIdx.x;
    int rank = blockIdx.x & 7;
    int btile = blockIdx.x >> 3;      // 0..15
    int b0 = btile * 16;
    int j0 = rank * 32;               // my 32 neurons

    { // Ws fill: Ws[k][c] = Whh[(c>>5)*HHH + j0 + (c&31)][k]; 128 k's per thread
        int c = tid & 127;
        int k0 = (tid >> 7) << 7;     // 0 or 128
        int grow = (c >> 5) * HHH + j0 + (c & 31);
        const float* src = Whh + (size_t)grow * HHH + k0;
        for (int kk = 0; kk < 128; ++kk) Ws[k0 + kk][c] = src[kk];
    }
    { // zero Hs (both buffers)
        float* hz = (float*)Hs;
        for (int i = tid; i < ENC_HS_F; i += 256) hz[i] = 0.f;
    }
    __syncthreads();
    CLUSTER_ARRIVE(); CLUSTER_WAIT();   // Hs zeroed everywhere before DSMEM writes

    const int r  = tid >> 4;          // row 0..15
    const int cg = tid & 15;          // 8 gate-cols: c = cg*8..cg*8+7
    const int gate = cg >> 2;
    const int jj8 = (cg & 3) * 8;     // neuron offset within my 32 (for xp)
    const float* wbase = &Ws[0][cg * 8];
    const int nj = (tid & 15) * 2;    // epilogue: neurons nj, nj+1 of row r
    const u32t h_laddr = (u32t)__cvta_generic_to_shared(&Hs[0][0][0]);
    const int hs_off_r = r * 256 + j0 + nj;   // within one buffer (floats)

    float c0 = 0.f, c1 = 0.f;

    // prologue xp load (t=0)
    const float* xpb = &g_xproj_enc[((size_t)(b0 + r) * TT) * 1024 + gate * HHH + j0 + jj8];
    ulonglong2 qa = *(const ulonglong2*)xpb;
    ulonglong2 qb = *(const ulonglong2*)(xpb + 4);

    for (int t = 0; t < TT; ++t) {
        u64t A0 = qa.x, A1 = qa.y, A2 = qb.x, A3 = qb.y;
        if (t + 1 < TT) { // prefetch next step's xp (consumed after cluster.sync)
            const float* xpn = xpb + (size_t)(t + 1) * 1024;
            qa = *(const ulonglong2*)xpn;
            qb = *(const ulonglong2*)(xpn + 4);
        }
        const float* hrow = &Hs[t & 1][r][0];
#pragma unroll 8
        for (int k = 0; k < HHH; ++k) {
            u64t H;
            PACK1(H, __float_as_uint(hrow[k]));
            const float* wk = wbase + (k << 7);
            ulonglong2 w0 = *(const ulonglong2*)wk;
            ulonglong2 w1 = *(const ulonglong2*)(wk + 4);
            FMA2(A0, H, w0.x, A0); FMA2(A1, H, w0.y, A1);
            FMA2(A2, H, w1.x, A2); FMA2(A3, H, w1.y, A3);
        }
        { // park 8 gate values
            u64t* gp = (u64t*)&Gs[r][cg * 8];
            gp[0] = A0; gp[1] = A1; gp[2] = A2; gp[3] = A3;
        }
        __syncthreads();

        // epilogue: 2 neurons (c in regs)
        float h0v, h1v;
        {
            float vi = Gs[r][nj], vf = Gs[r][32 + nj], vg = Gs[r][64 + nj], vo = Gs[r][96 + nj];
            float si = 1.f / (1.f + __expf(-vi));
            float sf = 1.f / (1.f + __expf(-vf));
            float tg = tanhf(vg);
            float so = 1.f / (1.f + __expf(-vo));
            c0 = fmaf(sf, c0, si * tg);
            h0v = so * tanhf(c0);
        }
        {
            float vi = Gs[r][nj+1], vf = Gs[r][32+nj+1], vg = Gs[r][64+nj+1], vo = Gs[r][96+nj+1];
            float si = 1.f / (1.f + __expf(-vi));
            float sf = 1.f / (1.f + __expf(-vf));
            float tg = tanhf(vg);
            float so = 1.f / (1.f + __expf(-vo));
            c1 = fmaf(sf, c1, si * tg);
            h1v = so * tanhf(c1);
        }
        // push h pair into every cluster CTA's Hs[next buf]
        u64t hv = ((u64t)__float_as_uint(h1v) << 32) | (u64t)__float_as_uint(h0v);
        u32t la = h_laddr + (u32t)(((((t + 1) & 1) * 16 * 256) + hs_off_r) * 4);
#pragma unroll
        for (int rk = 0; rk < 8; ++rk) dsmem_st64(la, rk, hv);
        // global enc_out store (overlaps barrier)
        *(float2*)&g_enc_out[((size_t)(b0 + r) * TT + t) * HHH + j0 + nj] = make_float2(h0v, h1v);

        CLUSTER_ARRIVE(); CLUSTER_WAIT();
    }
}

// ---------------- decoder recurrence: 16 clusters x 8 CTAs ----------------
// CTA owns 16 neurons (64 gate cols). Ws[128][64] 32KB + Hs[2][16][128] 16KB + Gs[16][68]
#define DEC_WS_F   (128 * 64)
#define DEC_HS_F   (2 * 16 * 128)
#define DEC_GS_F   (16 * 68)
#define DEC_SMEM_BYTES ((DEC_WS_F + DEC_HS_F + DEC_GS_F) * 4)

__global__ __launch_bounds__(256) __cluster_dims__(8, 1, 1)
void dec_rec_kernel(const float* __restrict__ Whh, float* __restrict__ out)
{
    extern __shared__ float sm[];
    float (*Ws)[64] = (float(*)[64])sm;                        // [k][c], c=gate*16+jj
    float (*Hs)[16][128] = (float(*)[16][128])(sm + DEC_WS_F);
    float (*Gs)[68] = (float(*)[68])(sm + DEC_WS_F + DEC_HS_F);

    int tid = threadIdx.x;
    int rank = blockIdx.x & 7;
    int btile = blockIdx.x >> 3;
    int b0 = btile * 16;
    int j0 = rank * 16;

    { // Ws fill: Ws[k][c] = Whh[(c>>4)*DD + j0 + (c&15)][k]; 32 k's per thread
        int c = tid & 63;
        int k0 = (tid >> 6) << 5;     // 0,32,64,96
        int grow = (c >> 4) * DD + j0 + (c & 15);
        const float* src = Whh + (size_t)grow * DD + k0;
        for (int kk = 0; kk < 32; ++kk) Ws[k0 + kk][c] = src[kk];
    }
    {
        float* hz = (float*)Hs;
        for (int i = tid; i < DEC_HS_F; i += 256) hz[i] = 0.f;
    }
    __syncthreads();
    CLUSTER_ARRIVE(); CLUSTER_WAIT();

    const int r  = tid >> 4;          // row 0..15
    const int cg = tid & 15;          // 4 gate-cols: c = cg*4..cg*4+3
    const int gate = cg >> 2;
    const int jj4 = (cg & 3) * 4;
    const float* wbase = &Ws[0][cg * 4];
    const int nj = tid & 15;          // epilogue: 1 neuron of row r
    const u32t h_laddr = (u32t)__cvta_generic_to_shared(&Hs[0][0][0]);
    const int hs_off_r = r * 128 + j0 + nj;

    float cc = 0.f;

    const float* xpb = &g_xproj_dec[((size_t)(b0 + r) * TT) * 512 + gate * DD + j0 + jj4];
    ulonglong2 q = *(const ulonglong2*)xpb;

    for (int t = 0; t < TT; ++t) {
        u64t A0 = q.x, A1 = q.y;
        if (t + 1 < TT) q = *(const ulonglong2*)(xpb + (size_t)(t + 1) * 512);

        const float* hrow = &Hs[t & 1][r][0];
#pragma unroll 8
        for (int k = 0; k < DD; ++k) {
            u64t H;
            PACK1(H, __float_as_uint(hrow[k]));
            ulonglong2 w = *(const ulonglong2*)(wbase + (k << 6));
            FMA2(A0, H, w.x, A0);
            FMA2(A1, H, w.y, A1);
        }
        {
            u64t* gp = (u64t*)&Gs[r][cg * 4];
            gp[0] = A0; gp[1] = A1;
        }
        __syncthreads();

        float hv;
        {
            float vi = Gs[r][nj], vf = Gs[r][16 + nj], vg = Gs[r][32 + nj], vo = Gs[r][48 + nj];
            float si = 1.f / (1.f + __expf(-vi));
            float sf = 1.f / (1.f + __expf(-vf));
            float tg = tanhf(vg);
            float so = 1.f / (1.f + __expf(-vo));
            cc = fmaf(sf, cc, si * tg);
            hv = so * tanhf(cc);
        }
        u32t la = h_laddr + (u32t)(((((t + 1) & 1) * 16 * 128) + hs_off_r) * 4);
#pragma unroll
        for (int rk = 0; rk < 8; ++rk) dsmem_st32(la, rk, hv);
        out[((size_t)(b0 + r) * TT + t) * DD + j0 + nj] = hv;

        CLUSTER_ARRIVE(); CLUSTER_WAIT();
    }
}

// ---------------- launch ----------------
extern "C" void kernel_launch(void* const* d_in, const int* in_sizes, int n_in,
                              void* d_out, int out_size) {
    const float* x    = (const float*)d_in[0];
    const float* eWih = (const float*)d_in[1];
    const float* eWhh = (const float*)d_in[2];
    const float* ebih = (const float*)d_in[3];
    const float* ebhh = (const float*)d_in[4];
    const float* dWih = (const float*)d_in[5];
    const float* dWhh = (const float*)d_in[6];
    const float* dbih = (const float*)d_in[7];
    const float* dbhh = (const float*)d_in[8];
    float* out = (float*)d_out;

    cudaFuncSetAttribute(enc_rec_kernel,
                         cudaFuncAttributeMaxDynamicSharedMemorySize, ENC_SMEM_BYTES);
    cudaFuncSetAttribute(dec_rec_kernel,
                         cudaFuncAttributeMaxDynamicSharedMemorySize, DEC_SMEM_BYTES);

    // x_proj_enc = x @ eWih^T + biases : M=65536, N=1024, K=128
    proj_kernel<128><<<dim3(8, 512), 256>>>(x, eWih, ebih, ebhh, 0, 0, 1024);
    dummy_kernel<<<1, 32>>>();
    dummy_kernel<<<1, 32>>>();   // keeps enc_rec in ncu's capture slot (#4)
    enc_rec_kernel<<<128, 256, ENC_SMEM_BYTES>>>(eWhh);
    // x_proj_dec = encoded @ dWih^T + biases : M=65536, N=512, K=256
    proj_kernel<256><<<dim3(4, 512), 256>>>(nullptr, dWih, dbih, dbhh, 1, 1, 512);
    dec_rec_kernel<<<128, 256, DEC_SMEM_BYTES>>>(dWhh, out);
}

// round 16
// speedup vs baseline: 1.7736x; 1.7736x over previous
#include <cuda_runtime.h>

#define BB 256
#define TT 256
#define DD 128
#define HHH 256

typedef unsigned long long u64t;
typedef unsigned int u32t;

// Blackwell packed fp32 ops (PTX-only; ptxas won't emit FFMA2 from C++)
#define FMA2(d,a,b,c) asm("fma.rn.f32x2 %0, %1, %2, %3;" : "=l"(d) : "l"(a), "l"(b), "l"(c))
#define PACK1(d,x)    asm("mov.b64 %0, {%1, %1};" : "=l"(d) : "r"(x))
#define UNPK(lo,hi,v) asm("mov.b64 {%0, %1}, %2;" : "=r"(lo), "=r"(hi) : "l"(v))

// release/acquire flag ops (no full membar drains)
#define ST_REL(p,v) asm volatile("st.release.gpu.global.s32 [%0], %1;" :: "l"(p), "r"(v) : "memory")
#define LD_ACQ(v,p) asm volatile("ld.acquire.gpu.global.s32 %0, [%1];" : "=r"(v) : "l"(p) : "memory")

// ---------------- scratch (device globals; no allocations) ----------------
__device__ float g_xproj_enc[(size_t)BB * TT * 4 * HHH];  // 256 MB
__device__ float g_xproj_dec[(size_t)BB * TT * 4 * DD];   // 128 MB
__device__ float g_enc_out[(size_t)BB * TT * HHH];        // 64 MB
__device__ float g_hbuf_enc[2][BB][HHH];
__device__ float g_hbuf_dec[2][BB][DD];
__device__ int g_flag_enc[4][32];   // per btile: one slot per slice CTA
__device__ int g_flag_dec[4][32];

// ---------------- init: zero h0 buffers + flags ----------------
__global__ void init_kernel() {
    int tid = blockIdx.x * blockDim.x + threadIdx.x;
    int stride = gridDim.x * blockDim.x;
    float* he = &g_hbuf_enc[0][0][0];
    float* hd = &g_hbuf_dec[0][0][0];
    for (int i = tid; i < 2 * BB * HHH; i += stride) he[i] = 0.f;
    for (int i = tid; i < 2 * BB * DD; i += stride) hd[i] = 0.f;
    if (tid < 128) {
        (&g_flag_enc[0][0])[tid] = 0;
        (&g_flag_dec[0][0])[tid] = 0;
    }
}

// ---------------- input-projection GEMM: C[M,N] = A[M,K] @ W[N,K]^T + b1 + b2
// 128x128 tiles, BK=8, 256 threads, 8x8 micro-tile, packed f32x2 FMA.
template <int K>
__global__ __launch_bounds__(256) void proj_kernel(
    const float* __restrict__ Ain, const float* __restrict__ W,
    const float* __restrict__ b1, const float* __restrict__ b2,
    int src_sel, int dst_sel, int N)
{
    const float* A = src_sel ? (const float*)g_enc_out : Ain;
    float* C = dst_sel ? (float*)g_xproj_dec : (float*)g_xproj_enc;

    __shared__ float As[8][128];
    __shared__ float Bs[8][128];
    int tid = threadIdx.x;
    int bn = blockIdx.x, bm = blockIdx.y;
    int tr = tid >> 4, tc = tid & 15;   // 16x16 thread grid
    int lr = tid >> 1;                  // stage row 0..127
    int lk = (tid & 1) << 2;            // 0 or 4

    const float* Ag = A + (size_t)(bm * 128 + lr) * K + lk;
    const float* Wg = W + (size_t)(bn * 128 + lr) * K + lk;

    u64t acc[8][4];
#pragma unroll
    for (int i = 0; i < 8; ++i)
#pragma unroll
        for (int j = 0; j < 4; ++j) acc[i][j] = 0ULL;

    for (int kb = 0; kb < K; kb += 8) {
        float4 av = *(const float4*)(Ag + kb);
        float4 wv = *(const float4*)(Wg + kb);
        __syncthreads();
        As[lk + 0][lr] = av.x; As[lk + 1][lr] = av.y;
        As[lk + 2][lr] = av.z; As[lk + 3][lr] = av.w;
        Bs[lk + 0][lr] = wv.x; Bs[lk + 1][lr] = wv.y;
        Bs[lk + 2][lr] = wv.z; Bs[lk + 3][lr] = wv.w;
        __syncthreads();
#pragma unroll
        for (int kk = 0; kk < 8; ++kk) {
            float4 alo = *(const float4*)&As[kk][tr * 4];
            float4 ahi = *(const float4*)&As[kk][64 + tr * 4];
            ulonglong2 wlo = *(const ulonglong2*)&Bs[kk][tc * 4];
            ulonglong2 whi = *(const ulonglong2*)&Bs[kk][64 + tc * 4];
            float ar[8] = {alo.x, alo.y, alo.z, alo.w, ahi.x, ahi.y, ahi.z, ahi.w};
#pragma unroll
            for (int i = 0; i < 8; ++i) {
                u64t a2; PACK1(a2, __float_as_uint(ar[i]));
                FMA2(acc[i][0], a2, wlo.x, acc[i][0]);
                FMA2(acc[i][1], a2, wlo.y, acc[i][1]);
                FMA2(acc[i][2], a2, whi.x, acc[i][2]);
                FMA2(acc[i][3], a2, whi.y, acc[i][3]);
            }
        }
    }
    int c_lo = bn * 128 + tc * 4;
    int c_hi = c_lo + 64;
    float4 v1 = *(const float4*)&b1[c_lo];
    float4 v2 = *(const float4*)&b2[c_lo];
    float4 blo = make_float4(v1.x + v2.x, v1.y + v2.y, v1.z + v2.z, v1.w + v2.w);
    float4 u1 = *(const float4*)&b1[c_hi];
    float4 u2 = *(const float4*)&b2[c_hi];
    float4 bhi = make_float4(u1.x + u2.x, u1.y + u2.y, u1.z + u2.z, u1.w + u2.w);
#pragma unroll
    for (int i = 0; i < 8; ++i) {
        int row = bm * 128 + (i < 4 ? tr * 4 + i : 64 + tr * 4 + (i - 4));
        u32t l0, h0, l1, h1;
        UNPK(l0, h0, acc[i][0]); UNPK(l1, h1, acc[i][1]);
        float4 o0 = make_float4(__uint_as_float(l0) + blo.x, __uint_as_float(h0) + blo.y,
                                __uint_as_float(l1) + blo.z, __uint_as_float(h1) + blo.w);
        *(float4*)&C[(size_t)row * N + c_lo] = o0;
        UNPK(l0, h0, acc[i][2]); UNPK(l1, h1, acc[i][3]);
        float4 o1 = make_float4(__uint_as_float(l0) + bhi.x, __uint_as_float(h0) + bhi.y,
                                __uint_as_float(l1) + bhi.z, __uint_as_float(h1) + bhi.w);
        *(float4*)&C[(size_t)row * N + c_hi] = o1;
    }
}

// ---------------- encoder recurrence: persistent, 128 CTAs ----------------
// CTA = 64 batch rows x 8 neurons (32 gate-cols). Whh slice in smem once.
// Barrier: per-CTA release flag + 32-lane coalesced acquire poll (no atomics).
#define ENC_SMEM_BYTES ((8192 + 16640 + 2112 + 512) * 4)

__global__ __launch_bounds__(256) void enc_rec_kernel(const float* __restrict__ Whh)
{
    extern __shared__ float sm[];
    float (*Ws)[32]  = (float(*)[32])sm;
    float (*Hs)[260] = (float(*)[260])(sm + 8192);
    float (*Gs)[33]  = (float(*)[33])(sm + 8192 + 16640);
    float (*Cs)[8]   = (float(*)[8])(sm + 8192 + 16640 + 2112);

    int tid = threadIdx.x;
    int slice = blockIdx.x & 31;   // 0..31 (neuron slices of 8)
    int btile = blockIdx.x >> 5;   // 0..3  (batch tiles of 64)
    int b0 = btile * 64;
    int j0 = slice * 8;

    // load Whh slice transposed: Ws[k][c], c = gate*8 + jj
    {
        int c = tid & 31;
        int k0 = (tid >> 5) << 5;
        int grow = (c >> 3) * HHH + j0 + (c & 7);
        const float* src = Whh + (size_t)grow * HHH + k0;
#pragma unroll
        for (int kk = 0; kk < 32; ++kk) Ws[k0 + kk][c] = src[kk];
    }
    for (int i = tid; i < 512; i += 256) ((float*)Cs)[i] = 0.f;
    __syncthreads();

    const int tr2 = (tid >> 3) << 1;                     // row pair 0..62
    const int tc4 = (tid & 7) << 2;                      // col quad 0..28
    const int gci = (tc4 >> 3) * HHH + j0 + (tc4 & 7);   // global gate col
    const float* hr0 = &Hs[tr2][0];
    const float* hr1 = &Hs[tr2 + 1][0];
    const float* wcol = &Ws[0][tc4];

    // xp prologue load (t = 0)
    const float* xpb = &g_xproj_enc[((size_t)(b0 + tr2) * TT) * 1024 + gci];
    ulonglong2 q0 = *(const ulonglong2*)xpb;
    ulonglong2 q1 = *(const ulonglong2*)(xpb + (size_t)TT * 1024);

    for (int t = 0; t < TT; ++t) {
        u64t A00 = q0.x, A01 = q0.y, A10 = q1.x, A11 = q1.y;
        if (t + 1 < TT) {   // prefetch next step's xp (DRAM latency hides under this step)
            const float* xpn = xpb + (size_t)(t + 1) * 1024;
            q0 = *(const ulonglong2*)xpn;
            q1 = *(const ulonglong2*)(xpn + (size_t)TT * 1024);
        }

        { // stage h_prev tile [64][256] from global double buffer
            int r = tid >> 2;
            int k0 = (tid & 3) << 6;
            const float* hp = &g_hbuf_enc[t & 1][b0 + r][k0];
            float* dst = &Hs[r][k0];
#pragma unroll
            for (int kk = 0; kk < 64; kk += 4)
                *(float4*)(dst + kk) = *(const float4*)(hp + kk);
        }
        __syncthreads();

#pragma unroll 8
        for (int k = 0; k < HHH; ++k) {
            u64t H0, H1;
            PACK1(H0, __float_as_uint(hr0[k]));
            PACK1(H1, __float_as_uint(hr1[k]));
            ulonglong2 w = *(const ulonglong2*)(wcol + (k << 5));
            FMA2(A00, H0, w.x, A00); FMA2(A01, H0, w.y, A01);
            FMA2(A10, H1, w.x, A10); FMA2(A11, H1, w.y, A11);
        }
        {
            u32t l, h;
            UNPK(l, h, A00); Gs[tr2][tc4 + 0] = __uint_as_float(l); Gs[tr2][tc4 + 1] = __uint_as_float(h);
            UNPK(l, h, A01); Gs[tr2][tc4 + 2] = __uint_as_float(l); Gs[tr2][tc4 + 3] = __uint_as_float(h);
            UNPK(l, h, A10); Gs[tr2 + 1][tc4 + 0] = __uint_as_float(l); Gs[tr2 + 1][tc4 + 1] = __uint_as_float(h);
            UNPK(l, h, A11); Gs[tr2 + 1][tc4 + 2] = __uint_as_float(l); Gs[tr2 + 1][tc4 + 3] = __uint_as_float(h);
        }
        __syncthreads();

        float hsave[2];
#pragma unroll
        for (int q = 0; q < 2; ++q) {
            int p = tid + q * 256;
            int r = p >> 3, j = p & 7;
            float vi = Gs[r][j], vf = Gs[r][8 + j], vg = Gs[r][16 + j], vo = Gs[r][24 + j];
            float si = 1.f / (1.f + __expf(-vi));
            float sf = 1.f / (1.f + __expf(-vf));
            float tg = tanhf(vg);
            float so = 1.f / (1.f + __expf(-vo));
            float cv = fmaf(sf, Cs[r][j], si * tg);
            Cs[r][j] = cv;
            float h = so * tanhf(cv);
            g_hbuf_enc[(t + 1) & 1][b0 + r][j0 + j] = h;
            hsave[q] = h;
        }
        __syncthreads();   // all h stores issued (CTA-wide happens-before tid0's release)
        if (tid == 0) ST_REL(&g_flag_enc[btile][slice], t + 1);
        // deferred enc_out stores overlap the poll
#pragma unroll
        for (int q = 0; q < 2; ++q) {
            int p = tid + q * 256;
            int r = p >> 3, j = p & 7;
            g_enc_out[((size_t)(b0 + r) * TT + t) * HHH + j0 + j] = hsave[q];
        }
        if (tid < 32) {   // one coalesced LDG polls all 32 peer flags
            const int* fp = &g_flag_enc[btile][tid];
            int v;
            while (true) {
                LD_ACQ(v, fp);
                if (!__ballot_sync(0xffffffffu, v <= t)) break;
                __nanosleep(32);
            }
        }
        __syncthreads();
    }
}

// ---------------- decoder recurrence: 128 CTAs, 64 rows x 4 neurons ------
__global__ __launch_bounds__(256) void dec_rec_kernel(
    const float* __restrict__ Whh, float* __restrict__ out)
{
    __shared__ float Ws[128][16];
    __shared__ float Hs[64][132];
    __shared__ float Gs[64][17];
    __shared__ float Cs[64][4];

    int tid = threadIdx.x;
    int slice = blockIdx.x & 31;   // 0..31 (neuron slices of 4)
    int btile = blockIdx.x >> 5;   // 0..3
    int b0 = btile * 64;
    int j0 = slice * 4;

    {
        int c = tid & 15;
        int k0 = (tid >> 4) << 3;
        int grow = (c >> 2) * DD + j0 + (c & 3);
        const float* src = Whh + (size_t)grow * DD + k0;
#pragma unroll
        for (int kk = 0; kk < 8; ++kk) Ws[k0 + kk][c] = src[kk];
    }
    if (tid < 256) ((float*)Cs)[tid] = 0.f;
    __syncthreads();

    const int tr2 = (tid >> 3) << 1;
    const int tc2 = (tid & 7) << 1;
    const int gci = (tc2 >> 2) * DD + j0 + (tc2 & 3);
    const float* hr0 = &Hs[tr2][0];
    const float* hr1 = &Hs[tr2 + 1][0];
    const float* wcol = &Ws[0][tc2];

    const float* xpb = &g_xproj_dec[((size_t)(b0 + tr2) * TT) * 512 + gci];
    u64t p0 = *(const u64t*)xpb;
    u64t p1 = *(const u64t*)(xpb + (size_t)TT * 512);

    for (int t = 0; t < TT; ++t) {
        u64t A0 = p0, A1 = p1;
        if (t + 1 < TT) {
            const float* xpn = xpb + (size_t)(t + 1) * 512;
            p0 = *(const u64t*)xpn;
            p1 = *(const u64t*)(xpn + (size_t)TT * 512);
        }

        {
            int r = tid >> 2;
            int k0 = (tid & 3) << 5;
            const float* hp = &g_hbuf_dec[t & 1][b0 + r][k0];
            float* dst = &Hs[r][k0];
#pragma unroll
            for (int kk = 0; kk < 32; kk += 4)
                *(float4*)(dst + kk) = *(const float4*)(hp + kk);
        }
        __syncthreads();

#pragma unroll 8
        for (int k = 0; k < DD; ++k) {
            u64t H0, H1;
            PACK1(H0, __float_as_uint(hr0[k]));
            PACK1(H1, __float_as_uint(hr1[k]));
            u64t w = *(const u64t*)(wcol + (k << 4));
            FMA2(A0, H0, w, A0);
            FMA2(A1, H1, w, A1);
        }
        {
            u32t l, h;
            UNPK(l, h, A0); Gs[tr2][tc2] = __uint_as_float(l); Gs[tr2][tc2 + 1] = __uint_as_float(h);
            UNPK(l, h, A1); Gs[tr2 + 1][tc2] = __uint_as_float(l); Gs[tr2 + 1][tc2 + 1] = __uint_as_float(h);
        }
        __syncthreads();

        float hsave;
        int r = tid >> 2, j = tid & 3;
        {
            float vi = Gs[r][j], vf = Gs[r][4 + j], vg = Gs[r][8 + j], vo = Gs[r][12 + j];
            float si = 1.f / (1.f + __expf(-vi));
            float sf = 1.f / (1.f + __expf(-vf));
            float tg = tanhf(vg);
            float so = 1.f / (1.f + __expf(-vo));
            float cv = fmaf(sf, Cs[r][j], si * tg);
            Cs[r][j] = cv;
            hsave = so * tanhf(cv);
            g_hbuf_dec[(t + 1) & 1][b0 + r][j0 + j] = hsave;
        }
        __syncthreads();
        if (tid == 0) ST_REL(&g_flag_dec[btile][slice], t + 1);
        out[((size_t)(b0 + r) * TT + t) * DD + j0 + j] = hsave;   // overlaps poll
        if (tid < 32) {
            const int* fp = &g_flag_dec[btile][tid];
            int v;
            while (true) {
                LD_ACQ(v, fp);
                if (!__ballot_sync(0xffffffffu, v <= t)) break;
                __nanosleep(32);
            }
        }
        __syncthreads();
    }
}

// ---------------- launch ----------------
extern "C" void kernel_launch(void* const* d_in, const int* in_sizes, int n_in,
                              void* d_out, int out_size) {
    const float* x    = (const float*)d_in[0];
    const float* eWih = (const float*)d_in[1];
    const float* eWhh = (const float*)d_in[2];
    const float* ebih = (const float*)d_in[3];
    const float* ebhh = (const float*)d_in[4];
    const float* dWih = (const float*)d_in[5];
    const float* dWhh = (const float*)d_in[6];
    const float* dbih = (const float*)d_in[7];
    const float* dbhh = (const float*)d_in[8];
    float* out = (float*)d_out;

    cudaFuncSetAttribute(enc_rec_kernel,
                         cudaFuncAttributeMaxDynamicSharedMemorySize, ENC_SMEM_BYTES);

    init_kernel<<<64, 256>>>();
    // x_proj_enc = x @ eWih^T + biases : M=65536, N=1024, K=128
    proj_kernel<128><<<dim3(8, 512), 256>>>(x, eWih, ebih, ebhh, 0, 0, 1024);
    enc_rec_kernel<<<128, 256, ENC_SMEM_BYTES>>>(eWhh);
    // x_proj_dec = encoded @ dWih^T + biases : M=65536, N=512, K=256
    proj_kernel<256><<<dim3(4, 512), 256>>>(nullptr, dWih, dbih, dbhh, 1, 1, 512);
    dec_rec_kernel<<<128, 256>>>(dWhh, out);
}

// round 17
// speedup vs baseline: 2.3172x; 1.3065x over previous
#include <cuda_runtime.h>

#define BB 256
#define TT 256
#define DD 128
#define HHH 256

typedef unsigned long long u64t;
typedef unsigned int u32t;

// Blackwell packed fp32 ops (PTX-only; ptxas won't emit FFMA2 from C++)
#define FMA2(d,a,b,c) asm("fma.rn.f32x2 %0, %1, %2, %3;" : "=l"(d) : "l"(a), "l"(b), "l"(c))
#define PACK1(d,x)    asm("mov.b64 %0, {%1, %1};" : "=l"(d) : "r"(x))
#define UNPK(lo,hi,v) asm("mov.b64 {%0, %1}, %2;" : "=r"(lo), "=r"(hi) : "l"(v))

// ---------------- scratch (device globals; no allocations) ----------------
__device__ float g_xproj_enc[(size_t)BB * TT * 4 * HHH];  // 256 MB
__device__ float g_xproj_dec[(size_t)BB * TT * 4 * DD];   // 128 MB
__device__ float g_enc_out[(size_t)BB * TT * HHH];        // 64 MB
__device__ float g_hbuf_enc[2][BB][HHH];
__device__ float g_hbuf_dec[2][BB][DD];
__device__ int g_ctr_enc[TT][4];   // per-step, per-btile (32-CTA groups)
__device__ int g_ctr_dec[TT][4];

// ---------------- init: zero h0 buffers + barrier counters ----------------
__global__ void init_kernel() {
    int tid = blockIdx.x * blockDim.x + threadIdx.x;
    int stride = gridDim.x * blockDim.x;
    float* he = &g_hbuf_enc[0][0][0];
    float* hd = &g_hbuf_dec[0][0][0];
    for (int i = tid; i < 2 * BB * HHH; i += stride) he[i] = 0.f;
    for (int i = tid; i < 2 * BB * DD; i += stride) hd[i] = 0.f;
    int* ce = &g_ctr_enc[0][0];
    int* cd = &g_ctr_dec[0][0];
    for (int i = tid; i < TT * 4; i += stride) { ce[i] = 0; cd[i] = 0; }
}

// ---------------- input-projection GEMM: C[M,N] = A[M,K] @ W[N,K]^T + b1 + b2
// 128x128 tiles, BK=8, 256 threads, 8x8 micro-tile, packed f32x2 FMA.
template <int K>
__global__ __launch_bounds__(256) void proj_kernel(
    const float* __restrict__ Ain, const float* __restrict__ W,
    const float* __restrict__ b1, const float* __restrict__ b2,
    int src_sel, int dst_sel, int N)
{
    const float* A = src_sel ? (const float*)g_enc_out : Ain;
    float* C = dst_sel ? (float*)g_xproj_dec : (float*)g_xproj_enc;

    __shared__ float As[8][128];
    __shared__ float Bs[8][128];
    int tid = threadIdx.x;
    int bn = blockIdx.x, bm = blockIdx.y;
    int tr = tid >> 4, tc = tid & 15;   // 16x16 thread grid
    int lr = tid >> 1;                  // stage row 0..127
    int lk = (tid & 1) << 2;            // 0 or 4

    const float* Ag = A + (size_t)(bm * 128 + lr) * K + lk;
    const float* Wg = W + (size_t)(bn * 128 + lr) * K + lk;

    u64t acc[8][4];
#pragma unroll
    for (int i = 0; i < 8; ++i)
#pragma unroll
        for (int j = 0; j < 4; ++j) acc[i][j] = 0ULL;

    for (int kb = 0; kb < K; kb += 8) {
        float4 av = *(const float4*)(Ag + kb);
        float4 wv = *(const float4*)(Wg + kb);
        __syncthreads();
        As[lk + 0][lr] = av.x; As[lk + 1][lr] = av.y;
        As[lk + 2][lr] = av.z; As[lk + 3][lr] = av.w;
        Bs[lk + 0][lr] = wv.x; Bs[lk + 1][lr] = wv.y;
        Bs[lk + 2][lr] = wv.z; Bs[lk + 3][lr] = wv.w;
        __syncthreads();
#pragma unroll
        for (int kk = 0; kk < 8; ++kk) {
            float4 alo = *(const float4*)&As[kk][tr * 4];
            float4 ahi = *(const float4*)&As[kk][64 + tr * 4];
            ulonglong2 wlo = *(const ulonglong2*)&Bs[kk][tc * 4];
            ulonglong2 whi = *(const ulonglong2*)&Bs[kk][64 + tc * 4];
            float ar[8] = {alo.x, alo.y, alo.z, alo.w, ahi.x, ahi.y, ahi.z, ahi.w};
#pragma unroll
            for (int i = 0; i < 8; ++i) {
                u64t a2; PACK1(a2, __float_as_uint(ar[i]));
                FMA2(acc[i][0], a2, wlo.x, acc[i][0]);
                FMA2(acc[i][1], a2, wlo.y, acc[i][1]);
                FMA2(acc[i][2], a2, whi.x, acc[i][2]);
                FMA2(acc[i][3], a2, whi.y, acc[i][3]);
            }
        }
    }
    int c_lo = bn * 128 + tc * 4;
    int c_hi = c_lo + 64;
    float4 v1 = *(const float4*)&b1[c_lo];
    float4 v2 = *(const float4*)&b2[c_lo];
    float4 blo = make_float4(v1.x + v2.x, v1.y + v2.y, v1.z + v2.z, v1.w + v2.w);
    float4 u1 = *(const float4*)&b1[c_hi];
    float4 u2 = *(const float4*)&b2[c_hi];
    float4 bhi = make_float4(u1.x + u2.x, u1.y + u2.y, u1.z + u2.z, u1.w + u2.w);
#pragma unroll
    for (int i = 0; i < 8; ++i) {
        int row = bm * 128 + (i < 4 ? tr * 4 + i : 64 + tr * 4 + (i - 4));
        u32t l0, h0, l1, h1;
        UNPK(l0, h0, acc[i][0]); UNPK(l1, h1, acc[i][1]);
        float4 o0 = make_float4(__uint_as_float(l0) + blo.x, __uint_as_float(h0) + blo.y,
                                __uint_as_float(l1) + blo.z, __uint_as_float(h1) + blo.w);
        *(float4*)&C[(size_t)row * N + c_lo] = o0;
        UNPK(l0, h0, acc[i][2]); UNPK(l1, h1, acc[i][3]);
        float4 o1 = make_float4(__uint_as_float(l0) + bhi.x, __uint_as_float(h0) + bhi.y,
                                __uint_as_float(l1) + bhi.z, __uint_as_float(h1) + bhi.w);
        *(float4*)&C[(size_t)row * N + c_hi] = o1;
    }
}

// ---------------- encoder recurrence: persistent, 128 CTAs ----------------
// CTA = 64 batch rows x 8 neurons (32 gate-cols). Whh slice in smem once.
// Barrier among the 32 CTAs of a batch tile (R14 skeleton, frozen).
#define ENC_SMEM_BYTES ((8192 + 16640 + 2112 + 512) * 4)

__global__ __launch_bounds__(256) void enc_rec_kernel(const float* __restrict__ Whh)
{
    extern __shared__ float sm[];
    float (*Ws)[32]  = (float(*)[32])sm;
    float (*Hs)[260] = (float(*)[260])(sm + 8192);
    float (*Gs)[33]  = (float(*)[33])(sm + 8192 + 16640);
    float (*Cs)[8]   = (float(*)[8])(sm + 8192 + 16640 + 2112);

    int tid = threadIdx.x;
    int slice = blockIdx.x & 31;   // 0..31 (neuron slices of 8)
    int btile = blockIdx.x >> 5;   // 0..3  (batch tiles of 64)
    int b0 = btile * 64;
    int j0 = slice * 8;

    // load Whh slice transposed: Ws[k][c], c = gate*8 + jj
    {
        int c = tid & 31;
        int k0 = (tid >> 5) << 5;
        int grow = (c >> 3) * HHH + j0 + (c & 7);
        const float* src = Whh + (size_t)grow * HHH + k0;
#pragma unroll
        for (int kk = 0; kk < 32; ++kk) Ws[k0 + kk][c] = src[kk];
    }
    for (int i = tid; i < 512; i += 256) ((float*)Cs)[i] = 0.f;
    __syncthreads();

    const int tr2 = (tid >> 3) << 1;                     // row pair 0..62
    const int tc4 = (tid & 7) << 2;                      // col quad 0..28
    const int gci = (tc4 >> 3) * HHH + j0 + (tc4 & 7);   // global gate col
    const float* hr0 = &Hs[tr2][0];
    const float* hr1 = &Hs[tr2 + 1][0];
    const float* wcol = &Ws[0][tc4];

    for (int t = 0; t < TT; ++t) {
        // xp loads issued FIRST: ~600cyc DRAM latency hides under staging+sync.
        // Values still initialize A (bit-identical accumulation order).
        const float* xp0 = &g_xproj_enc[((size_t)(b0 + tr2) * TT + t) * 1024 + gci];
        ulonglong2 q0 = *(const ulonglong2*)xp0;
        ulonglong2 q1 = *(const ulonglong2*)(xp0 + (size_t)TT * 1024);

        { // stage h_prev tile [64][256] from global double buffer
            int r = tid >> 2;
            int k0 = (tid & 3) << 6;
            const float* hp = &g_hbuf_enc[t & 1][b0 + r][k0];
            float* dst = &Hs[r][k0];
#pragma unroll
            for (int kk = 0; kk < 64; kk += 4)
                *(float4*)(dst + kk) = *(const float4*)(hp + kk);
        }
        __syncthreads();

        u64t A00 = q0.x, A01 = q0.y, A10 = q1.x, A11 = q1.y;
        // k-loop unrolled x4 with LDS.128 h loads: 6 LDS wf per 4k (was 12)
#pragma unroll 2
        for (int k = 0; k < HHH; k += 4) {
            float4 h0q = *(const float4*)(hr0 + k);
            float4 h1q = *(const float4*)(hr1 + k);
            float h0a[4] = {h0q.x, h0q.y, h0q.z, h0q.w};
            float h1a[4] = {h1q.x, h1q.y, h1q.z, h1q.w};
#pragma unroll
            for (int s = 0; s < 4; ++s) {
                u64t H0, H1;
                PACK1(H0, __float_as_uint(h0a[s]));
                PACK1(H1, __float_as_uint(h1a[s]));
                ulonglong2 w = *(const ulonglong2*)(wcol + ((k + s) << 5));
                FMA2(A00, H0, w.x, A00); FMA2(A01, H0, w.y, A01);
                FMA2(A10, H1, w.x, A10); FMA2(A11, H1, w.y, A11);
            }
        }
        {
            u32t l, h;
            UNPK(l, h, A00); Gs[tr2][tc4 + 0] = __uint_as_float(l); Gs[tr2][tc4 + 1] = __uint_as_float(h);
            UNPK(l, h, A01); Gs[tr2][tc4 + 2] = __uint_as_float(l); Gs[tr2][tc4 + 3] = __uint_as_float(h);
            UNPK(l, h, A10); Gs[tr2 + 1][tc4 + 0] = __uint_as_float(l); Gs[tr2 + 1][tc4 + 1] = __uint_as_float(h);
            UNPK(l, h, A11); Gs[tr2 + 1][tc4 + 2] = __uint_as_float(l); Gs[tr2 + 1][tc4 + 3] = __uint_as_float(h);
        }
        __syncthreads();

        float hsave[2];
#pragma unroll
        for (int q = 0; q < 2; ++q) {
            int p = tid + q * 256;
            int r = p >> 3, j = p & 7;
            float vi = Gs[r][j], vf = Gs[r][8 + j], vg = Gs[r][16 + j], vo = Gs[r][24 + j];
            float si = 1.f / (1.f + __expf(-vi));
            float sf = 1.f / (1.f + __expf(-vf));
            float tg = tanhf(vg);
            float so = 1.f / (1.f + __expf(-vo));
            float cv = fmaf(sf, Cs[r][j], si * tg);
            Cs[r][j] = cv;
            float h = so * tanhf(cv);
            g_hbuf_enc[(t + 1) & 1][b0 + r][j0 + j] = h;
            hsave[q] = h;
        }
        __syncthreads();                       // all h stores issued (happens-before tid0)
        int* ctr = &g_ctr_enc[t][btile];
        if (tid == 0) { __threadfence(); atomicAdd(ctr, 1); }   // single-thread release
        // deferred enc_out stores overlap the spin
#pragma unroll
        for (int q = 0; q < 2; ++q) {
            int p = tid + q * 256;
            int r = p >> 3, j = p & 7;
            g_enc_out[((size_t)(b0 + r) * TT + t) * HHH + j0 + j] = hsave[q];
        }
        if (tid == 0) {
            while (*(volatile int*)ctr < 32) __nanosleep(32);
            __threadfence();
        }
        __syncthreads();
    }
}

// ---------------- decoder recurrence: 128 CTAs, 64 rows x 4 neurons ------
__global__ __launch_bounds__(256) void dec_rec_kernel(
    const float* __restrict__ Whh, float* __restrict__ out)
{
    __shared__ float Ws[128][16];
    __shared__ float Hs[64][132];
    __shared__ float Gs[64][17];
    __shared__ float Cs[64][4];

    int tid = threadIdx.x;
    int slice = blockIdx.x & 31;   // 0..31 (neuron slices of 4)
    int btile = blockIdx.x >> 5;   // 0..3
    int b0 = btile * 64;
    int j0 = slice * 4;

    {
        int c = tid & 15;
        int k0 = (tid >> 4) << 3;
        int grow = (c >> 2) * DD + j0 + (c & 3);
        const float* src = Whh + (size_t)grow * DD + k0;
#pragma unroll
        for (int kk = 0; kk < 8; ++kk) Ws[k0 + kk][c] = src[kk];
    }
    if (tid < 256) ((float*)Cs)[tid] = 0.f;
    __syncthreads();

    const int tr2 = (tid >> 3) << 1;
    const int tc2 = (tid & 7) << 1;
    const int gci = (tc2 >> 2) * DD + j0 + (tc2 & 3);
    const float* hr0 = &Hs[tr2][0];
    const float* hr1 = &Hs[tr2 + 1][0];
    const float* wcol = &Ws[0][tc2];

    for (int t = 0; t < TT; ++t) {
        // xp loads first (latency hidden under staging+sync)
        const float* xp0 = &g_xproj_dec[((size_t)(b0 + tr2) * TT + t) * 512 + gci];
        u64t p0 = *(const u64t*)xp0;
        u64t p1 = *(const u64t*)(xp0 + (size_t)TT * 512);

        {
            int r = tid >> 2;
            int k0 = (tid & 3) << 5;
            const float* hp = &g_hbuf_dec[t & 1][b0 + r][k0];
            float* dst = &Hs[r][k0];
#pragma unroll
            for (int kk = 0; kk < 32; kk += 4)
                *(float4*)(dst + kk) = *(const float4*)(hp + kk);
        }
        __syncthreads();

        u64t A0 = p0, A1 = p1;
#pragma unroll 2
        for (int k = 0; k < DD; k += 4) {
            float4 h0q = *(const float4*)(hr0 + k);
            float4 h1q = *(const float4*)(hr1 + k);
            float h0a[4] = {h0q.x, h0q.y, h0q.z, h0q.w};
            float h1a[4] = {h1q.x, h1q.y, h1q.z, h1q.w};
#pragma unroll
            for (int s = 0; s < 4; ++s) {
                u64t H0, H1;
                PACK1(H0, __float_as_uint(h0a[s]));
                PACK1(H1, __float_as_uint(h1a[s]));
                u64t w = *(const u64t*)(wcol + ((k + s) << 4));
                FMA2(A0, H0, w, A0);
                FMA2(A1, H1, w, A1);
            }
        }
        {
            u32t l, h;
            UNPK(l, h, A0); Gs[tr2][tc2] = __uint_as_float(l); Gs[tr2][tc2 + 1] = __uint_as_float(h);
            UNPK(l, h, A1); Gs[tr2 + 1][tc2] = __uint_as_float(l); Gs[tr2 + 1][tc2 + 1] = __uint_as_float(h);
        }
        __syncthreads();

        float hsave;
        int r = tid >> 2, j = tid & 3;
        {
            float vi = Gs[r][j], vf = Gs[r][4 + j], vg = Gs[r][8 + j], vo = Gs[r][12 + j];
            float si = 1.f / (1.f + __expf(-vi));
            float sf = 1.f / (1.f + __expf(-vf));
            float tg = tanhf(vg);
            float so = 1.f / (1.f + __expf(-vo));
            float cv = fmaf(sf, Cs[r][j], si * tg);
            Cs[r][j] = cv;
            hsave = so * tanhf(cv);
            g_hbuf_dec[(t + 1) & 1][b0 + r][j0 + j] = hsave;
        }
        __syncthreads();                       // happens-before tid0's fence
        int* ctr = &g_ctr_dec[t][btile];
        if (tid == 0) { __threadfence(); atomicAdd(ctr, 1); }
        out[((size_t)(b0 + r) * TT + t) * DD + j0 + j] = hsave;   // overlaps spin
        if (tid == 0) {
            while (*(volatile int*)ctr < 32) __nanosleep(32);
            __threadfence();
        }
        __syncthreads();
    }
}

// ---------------- launch ----------------
extern "C" void kernel_launch(void* const* d_in, const int* in_sizes, int n_in,
                              void* d_out, int out_size) {
    const float* x    = (const float*)d_in[0];
    const float* eWih = (const float*)d_in[1];
    const float* eWhh = (const float*)d_in[2];
    const float* ebih = (const float*)d_in[3];
    const float* ebhh = (const float*)d_in[4];
    const float* dWih = (const float*)d_in[5];
    const float* dWhh = (const float*)d_in[6];
    const float* dbih = (const float*)d_in[7];
    const float* dbhh = (const float*)d_in[8];
    float* out = (float*)d_out;

    cudaFuncSetAttribute(enc_rec_kernel,
                         cudaFuncAttributeMaxDynamicSharedMemorySize, ENC_SMEM_BYTES);

    init_kernel<<<64, 256>>>();
    // x_proj_enc = x @ eWih^T + biases : M=65536, N=1024, K=128
    proj_kernel<128><<<dim3(8, 512), 256>>>(x, eWih, ebih, ebhh, 0, 0, 1024);
    enc_rec_kernel<<<128, 256, ENC_SMEM_BYTES>>>(eWhh);
    // x_proj_dec = encoded @ dWih^T + biases : M=65536, N=512, K=256
    proj_kernel<256><<<dim3(4, 512), 256>>>(nullptr, dWih, dbih, dbhh, 1, 1, 512);
    dec_rec_kernel<<<128, 256>>>(dWhh, out);
}